// round 11
// baseline (speedup 1.0000x reference)
#include <cuda_runtime.h>
#include <cstdint>

#define CELL_F     30
#define TPB        128
#define NWARP      (TPB / 32)
#define WT         32                          // cells per warp-tile
#define HEAD_F2    5                           // float2 per cell per tensor staged (floats 0..9)
#define HEAD_B     (HEAD_F2 * 8)               // 40 B
#define STAGE_B    (2 * WT * HEAD_B)           // 2560 (p-heads 1280 | g-heads 1280)
#define WARP_B     (2 * STAGE_B)               // 5120 (2 stages)
#define CLS_F2     10                          // cls float2 per cell (floats 10..29)
#define TILE_F2    (WT * 15)                   // 480 float2 per tensor per tile
#define GRID_MAX   1480                        // ~10 blocks/SM * 148

__device__ float        g_partials[2048];
__device__ unsigned int g_count = 0;

__device__ __forceinline__ void cp_async8(uint32_t saddr, const void* gaddr) {
    asm volatile("cp.async.ca.shared.global [%0], [%1], 8;\n"
                 :: "r"(saddr), "l"(gaddr) : "memory");
}
__device__ __forceinline__ void cp_commit() {
    asm volatile("cp.async.commit_group;\n" ::: "memory");
}
__device__ __forceinline__ void cp_wait1() {
    asm volatile("cp.async.wait_group 1;\n" ::: "memory");
}

__device__ __forceinline__ float softp(float x) {      // log(1+e^x), |x| small
    return __logf(1.0f + __expf(x));
}
__device__ __forceinline__ float sigm(float x) {
    return __fdividef(1.0f, 1.0f + __expf(-x));
}
__device__ __forceinline__ float sqrt_ap(float x) {
    float r; asm("sqrt.approx.f32 %0, %1;" : "=f"(r) : "f"(x)); return r;
}
__device__ __forceinline__ float iou_f(float al, float at, float ar, float ab,
                                       float bl, float bt, float br, float bb,
                                       float area_a, float area_b) {
    float ltx = fmaxf(al, bl), lty = fmaxf(at, bt);
    float rbx = fminf(ar, br), rby = fminf(ab, bb);
    float wx = fmaxf(rbx - ltx, 0.0f), wy = fmaxf(rby - lty, 0.0f);
    float inter = wx * wy;
    return __fdividef(inter, area_a + area_b - inter + 1e-7f);
}

__global__ void __launch_bounds__(TPB)
k_main(const float* __restrict__ p, const float* __restrict__ g,
       int ncells, int ntiles, float* __restrict__ out, double inv_batch) {
    __shared__ float s[NWARP * WARP_B / 4];    // per-warp 2-stage head buffers (20,480 B)
    __shared__ float wsum[NWARP];
    __shared__ double wdsum[TPB / 32];
    __shared__ unsigned int s_ticket;

    const int tid  = threadIdx.x;
    const int w    = tid >> 5;
    const int lane = tid & 31;
    float* swp = s + w * (WARP_B / 4);
    const uint32_t swb = (uint32_t)__cvta_generic_to_shared(swp);

    const int S  = gridDim.x * NWARP;          // warp-streams
    const int ws = blockIdx.x * NWARP + w;

    // ---- stage the 40B heads of one tile (5 cp.async8 per lane per tensor) ----
    auto prefetch = [&](int stage, int t) {
        if (t < ntiles) {
            int nv = ncells - t * WT; if (nv > WT) nv = WT;
            const ulonglong1* p8 = reinterpret_cast<const ulonglong1*>(p) + (long long)t * TILE_F2;
            const ulonglong1* g8 = reinterpret_cast<const ulonglong1*>(g) + (long long)t * TILE_F2;
            uint32_t sp_ = swb + (uint32_t)stage * STAGE_B;
            uint32_t sg_ = sp_ + WT * HEAD_B;
            #pragma unroll
            for (int k = 0; k < HEAD_F2; k++) {
                int idx = lane + k * 32;               // 0..159 chunk of this tile's heads
                int ci  = idx / HEAD_F2;
                int h   = idx - ci * HEAD_F2;
                if (ci < nv) {
                    int gi = ci * 15 + h;              // global 8B-chunk within tile
                    uint32_t so = (uint32_t)(ci * HEAD_B + h * 8);
                    cp_async8(sp_ + so, p8 + gi);
                    cp_async8(sg_ + so, g8 + gi);
                }
            }
        }
        cp_commit();
    };

    prefetch(0, ws);
    prefetch(1, ws + S);

    float acc = 0.0f;
    int it = 0;
    for (int t = ws; t < ntiles; t += S, it++) {
        cp_wait1();
        __syncwarp();

        const int stage = it & 1;
        const float* ph = swp + stage * (STAGE_B / 4);       // p heads: 10 floats/cell
        const float* gh = ph + (WT * HEAD_B / 4);            // g heads
        int nv = ncells - t * WT; if (nv > WT) nv = WT;

        // ================= head phase: own cell = t*WT + lane =================
        {
            bool valid = lane < nv;
            int ci = valid ? lane : 0;
            const float2* P2 = reinterpret_cast<const float2*>(ph) + ci * HEAD_F2;
            const float2* G2 = reinterpret_cast<const float2*>(gh) + ci * HEAD_F2;
            float2 Pa = P2[0], Pb_ = P2[1], Pc = P2[2], Pd = P2[3], Pe = P2[4];
            float2 Ga = G2[0], Gb_ = G2[1], Gc = G2[2], Gd = G2[3], Ge = G2[4];
            float conf_g = Ge.x;
            bool pos  = valid && (conf_g > 0.0f);
            bool zero = valid && (conf_g == 0.0f);

            int cell = t * WT + lane;
            int ij = cell % 49;
            int r  = ij / 7;
            int c  = ij - r * 7;
            float colf = (float)c, rowf = (float)r;

            float sx0 = sigm(Pa.x), sy0 = sigm(Pa.y), pw0 = Pb_.x, ph0 = Pb_.y;
            float sx1 = sigm(Pc.x), sy1 = sigm(Pc.y), pw1 = Pd.x,  ph1 = Pd.y;
            float gx0 = Ga.x, gy0 = Ga.y, gw0 = Gb_.x, gh0 = Gb_.y;
            float gx1 = Gc.x, gy1 = Gc.y, gw1 = Gd.x,  gh1 = Gd.y;

            // IoU in 7x-scaled coords (scale-invariant)
            float pcx0 = sx0 + colf, pcy0 = sy0 + rowf;
            float pcx1 = sx1 + colf, pcy1 = sy1 + rowf;
            float gcx0 = gx0 + colf, gcy0 = gy0 + rowf;
            float gcx1 = gx1 + colf, gcy1 = gy1 + rowf;
            const float H = 3.5f;

            float pl0 = pcx0 - pw0 * H, pt0 = pcy0 - ph0 * H;
            float pr_0 = pcx0 + pw0 * H, pb0 = pcy0 + ph0 * H;
            float pl1 = pcx1 - pw1 * H, pt1 = pcy1 - ph1 * H;
            float pr_1 = pcx1 + pw1 * H, pb1 = pcy1 + ph1 * H;
            float gl0 = gcx0 - gw0 * H, gt0 = gcy0 - gh0 * H;
            float gr0 = gcx0 + gw0 * H, gb0 = gcy0 + gh0 * H;
            float gl1 = gcx1 - gw1 * H, gt1 = gcy1 - gh1 * H;
            float gr1 = gcx1 + gw1 * H, gb1 = gcy1 + gh1 * H;

            float ap0 = (pr_0 - pl0) * (pb0 - pt0);
            float ap1 = (pr_1 - pl1) * (pb1 - pt1);
            float ag0 = (gr0 - gl0) * (gb0 - gt0);
            float ag1 = (gr1 - gl1) * (gb1 - gt1);

            float i00 = iou_f(pl0, pt0, pr_0, pb0, gl0, gt0, gr0, gb0, ap0, ag0);
            float i10 = iou_f(pl1, pt1, pr_1, pb1, gl0, gt0, gr0, gb0, ap1, ag0);
            float i01 = iou_f(pl0, pt0, pr_0, pb0, gl1, gt1, gr1, gb1, ap0, ag1);
            float i11 = iou_f(pl1, pt1, pr_1, pb1, gl1, gt1, gr1, gb1, ap1, ag1);

            bool ind0 = i10 > i00;     // jnp.argmax: first max wins
            bool ind1 = i11 > i01;

            bool same_g   = (gx0 == gx1) && (gy0 == gy1) && (gw0 == gw1) && (gh0 == gh1);
            bool same_ind = (ind0 == ind1);

            float sqw0 = sqrt_ap(fabsf(pw0)), sqh0 = sqrt_ap(fabsf(ph0));
            float sqw1 = sqrt_ap(fabsf(pw1)), sqh1 = sqrt_ap(fabsf(ph1));
            float sgw0 = sqrt_ap(gw0), sgh0 = sqrt_ap(gh0);
            float sgw1 = sqrt_ap(gw1), sgh1 = sqrt_ap(gh1);

            #define BLOSS(px, py, qw, qh, qx, qy, rw, rh)                         \
                ((px - qx) * (px - qx) + (py - qy) * (py - qy) +                  \
                 (qw - rw) * (qw - rw) + (qh - rh) * (qh - rh))
            float l00 = BLOSS(sx0, sy0, sqw0, sqh0, gx0, gy0, sgw0, sgh0);
            float l10 = BLOSS(sx1, sy1, sqw1, sqh1, gx0, gy0, sgw0, sgh0);
            float l01 = BLOSS(sx0, sy0, sqw0, sqh0, gx1, gy1, sgw1, sgh1);
            float l11 = BLOSS(sx1, sy1, sqw1, sqh1, gx1, gy1, sgw1, sgh1);
            #undef BLOSS

            float lA = ind0 ? l10 : l00;
            float lB = l00 + l11;
            float lC = lA + (ind1 ? l11 : l01);
            float box_cell = same_g ? lA : (same_ind ? lB : lC);

            float pc0 = Pe.x, pc1 = Pe.y;
            float sp8 = softp(pc0), sp9 = softp(pc1);
            float confA  = ind1 ? (sp9 - pc1) : (sp8 - pc0);
            float confBC = (sp8 - pc0) + (sp9 - pc1);
            float conf_cell = same_g ? confA : confBC;

            float lossP = 5.0f * box_cell + conf_cell;       // cls added below
            float lossN = 0.5f * (sp8 + sp9);
            acc += pos ? lossP : (zero ? lossN : 0.0f);
        }

        // ===== cls phase: coalesced LDG of floats 10..29, masked log-product =====
        {
            const float2* Pg = reinterpret_cast<const float2*>(p) + (long long)t * TILE_F2;
            const float2* Gg = reinterpret_cast<const float2*>(g) + (long long)t * TILE_F2;
            float f0 = 1.0f, f1 = 1.0f, dot = 0.0f;
            #pragma unroll
            for (int k = 0; k < CLS_F2; k++) {
                int e  = lane + k * 32;                // cls-element index 0..319
                bool ok = e < nv * CLS_F2;
                int ee = ok ? e : 0;
                int ci = ee / CLS_F2;                  // owning cell
                int f  = ee + 5 * ci + 5;              // global float2 index in tile
                float2 pv = Pg[f];
                float2 gv = Gg[f];
                float conf = gh[ci * (HEAD_B / 4) + 8];
                bool m = ok && (conf > 0.0f);
                float fac = (1.0f + __expf(pv.x)) * (1.0f + __expf(pv.y));
                if (k & 1) f1 *= m ? fac : 1.0f;
                else       f0 *= m ? fac : 1.0f;
                dot += m ? (pv.x * gv.x + pv.y * gv.y) : 0.0f;
            }
            acc += __logf(f0) + __logf(f1) - dot;
        }

        __syncwarp();                    // warp done reading this stage's heads
        prefetch(stage, t + 2 * S);      // exactly one commit
    }

    // ---------- block reduction (once per block) ----------
    float loss = acc;
    #pragma unroll
    for (int o = 16; o > 0; o >>= 1) loss += __shfl_xor_sync(0xFFFFFFFFu, loss, o);
    if (lane == 0) wsum[w] = loss;
    __syncthreads();
    if (tid == 0) {
        float bs = 0.0f;
        #pragma unroll
        for (int ww = 0; ww < NWARP; ww++) bs += wsum[ww];
        g_partials[blockIdx.x] = bs;
        __threadfence();
        s_ticket = atomicAdd(&g_count, 1u);
    }
    __syncthreads();

    // ---------- last block finalizes (fixed order; self-resetting; graph-safe) ----------
    if (s_ticket == gridDim.x - 1) {
        __threadfence();
        volatile float* vp = g_partials;
        double dacc = 0.0;
        for (int i = tid; i < (int)gridDim.x; i += TPB) dacc += (double)vp[i];
        #pragma unroll
        for (int o = 16; o > 0; o >>= 1) dacc += __shfl_xor_sync(0xFFFFFFFFu, dacc, o);
        if ((tid & 31) == 0) wdsum[tid >> 5] = dacc;
        __syncthreads();
        if (tid == 0) {
            double tot = 0.0;
            #pragma unroll
            for (int ww = 0; ww < TPB / 32; ww++) tot += wdsum[ww];
            *out = (float)(tot * inv_batch);
            g_count = 0;                 // restore for next graph replay
        }
    }
}

extern "C" void kernel_launch(void* const* d_in, const int* in_sizes, int n_in,
                              void* d_out, int out_size) {
    const float* p = (const float*)d_in[0];
    const float* g = (const float*)d_in[1];
    int total  = in_sizes[0];            // B*7*7*30
    int ncells = total / CELL_F;         // B*49
    int batch  = ncells / 49;
    int ntiles = (ncells + WT - 1) / WT;
    int nb = GRID_MAX;
    int nb_need = (ntiles + 2 * NWARP - 1) / (2 * NWARP);
    if (nb > nb_need) nb = nb_need;
    if (nb < 1) nb = 1;

    k_main<<<nb, TPB>>>(p, g, ncells, ntiles, (float*)d_out, 1.0 / (double)batch);
}

// round 13
// speedup vs baseline: 1.0982x; 1.0982x over previous
#include <cuda_runtime.h>
#include <cstdint>

#define CELL_F        30
#define TPB           128
#define WT            32                        // cells per tile
#define WT_FLOATS     (WT * CELL_F)             // 960 per tensor
#define WT_F4         (WT_FLOATS / 4)           // 240
#define STAGE_FLOATS  (2 * WT_FLOATS)           // 1920 (p | g)
#define STAGE_BYTES   (STAGE_FLOATS * 4)        // 7680
#define PAIR_FLOATS   (2 * STAGE_FLOATS)        // 3840 (2 stages)
#define NPAIR         (TPB / 64)                // 2 pairs per block
#define GRID_MAX      1036                      // 7 blocks/SM * 148

__device__ float        g_partials[2048];
__device__ unsigned int g_count = 0;

__device__ __forceinline__ void cp_async16(uint32_t saddr, const void* gaddr) {
    asm volatile("cp.async.cg.shared.global [%0], [%1], 16;\n"
                 :: "r"(saddr), "l"(gaddr) : "memory");
}
__device__ __forceinline__ void cp_commit() {
    asm volatile("cp.async.commit_group;\n" ::: "memory");
}
__device__ __forceinline__ void cp_wait1() {
    asm volatile("cp.async.wait_group 1;\n" ::: "memory");
}

__device__ __forceinline__ float softp(float x) {      // log(1+e^x), |x| small
    return __logf(1.0f + __expf(x));
}
__device__ __forceinline__ float sigm(float x) {
    return __fdividef(1.0f, 1.0f + __expf(-x));
}
__device__ __forceinline__ float sqrt_ap(float x) {
    float r; asm("sqrt.approx.f32 %0, %1;" : "=f"(r) : "f"(x)); return r;
}
// intersection & denom (no division — IoUs feed only argmax)
__device__ __forceinline__ void iou_nd(float al, float at, float ar, float ab,
                                       float bl, float bt, float br, float bb,
                                       float area_a, float area_b,
                                       float& n, float& d) {
    float ltx = fmaxf(al, bl), lty = fmaxf(at, bt);
    float rbx = fminf(ar, br), rby = fminf(ab, bb);
    float wx = fmaxf(rbx - ltx, 0.0f), wy = fmaxf(rby - lty, 0.0f);
    n = wx * wy;
    d = area_a + area_b - n + 1e-7f;
}

__global__ void __launch_bounds__(TPB)
k_main(const float* __restrict__ p, const float* __restrict__ g,
       int ncells, int ntiles, float* __restrict__ out, double inv_batch) {
    __shared__ float s[NPAIR * PAIR_FLOATS];    // 30,720 B: per-pair 2-stage full tiles
    __shared__ float wsum[TPB / 32];
    __shared__ double wdsum[TPB / 32];
    __shared__ unsigned int s_ticket;

    const int tid  = threadIdx.x;
    const int w    = tid >> 5;
    const int lane = tid & 31;
    const int pair = w >> 1;
    const int role = w & 1;                     // 0: p-loader + head loss, 1: g-loader + cls loss
    float* sp = s + pair * PAIR_FLOATS;
    const uint32_t spb = (uint32_t)__cvta_generic_to_shared(sp);

    const int S  = gridDim.x * NPAIR;           // pair-streams
    const int ps = blockIdx.x * NPAIR + pair;
    const int barid = 1 + pair;

    // ---- stage own tensor's half of one tile (coalesced float4) ----
    auto prefetch = [&](int stage, int t) {
        if (t < ntiles) {
            if ((t + 1) * WT <= ncells) {
                const float4* src4 = reinterpret_cast<const float4*>(role ? g : p)
                                     + (long long)t * WT_F4;
                uint32_t dst = spb + (uint32_t)stage * STAGE_BYTES + (uint32_t)role * (WT_FLOATS * 4);
                #pragma unroll
                for (int k = 0; k < 8; k++) {
                    int i = lane + k * 32;
                    if (i < WT_F4) cp_async16(dst + i * 16, src4 + i);
                }
            } else {                            // ragged final tile: scalar staging
                int nf = (ncells - t * WT) * CELL_F;
                float* sd = sp + stage * STAGE_FLOATS + role * WT_FLOATS;
                const float* src = (role ? g : p) + (long long)t * WT_FLOATS;
                for (int ff = lane; ff < nf; ff += 32) sd[ff] = src[ff];
            }
        }
        cp_commit();
    };

    prefetch(0, ps);
    prefetch(1, ps + S);

    float acc = 0.0f;
    int it = 0;
    for (int t = ps; t < ntiles; t += S, it++) {
        cp_wait1();                              // own tensor's half of this stage is in
        asm volatile("bar.sync %0, 64;" :: "r"(barid) : "memory");   // partner's half too

        const float* sb = sp + (it & 1) * STAGE_FLOATS;
        int nv = ncells - t * WT; if (nv > WT) nv = WT;

        if (role == 0) {
            // ================= head loss: own cell = t*WT + lane =================
            bool valid = lane < nv;
            int ci = valid ? lane : 0;
            const float2* P2 = reinterpret_cast<const float2*>(sb) + ci * 15;
            const float2* G2 = reinterpret_cast<const float2*>(sb + WT_FLOATS) + ci * 15;
            float2 Pa = P2[0], Pb_ = P2[1], Pc = P2[2], Pd = P2[3], Pe = P2[4];
            float2 Ga = G2[0], Gb_ = G2[1], Gc = G2[2], Gd = G2[3], Ge = G2[4];
            float conf_g = Ge.x;
            bool pos  = valid && (conf_g > 0.0f);
            bool zero = valid && (conf_g == 0.0f);

            int cell = t * WT + lane;
            int ij = cell % 49;
            int r  = ij / 7;
            int c  = ij - r * 7;
            float colf = (float)c, rowf = (float)r;

            float sx0 = sigm(Pa.x), sy0 = sigm(Pa.y), pw0 = Pb_.x, ph0 = Pb_.y;
            float sx1 = sigm(Pc.x), sy1 = sigm(Pc.y), pw1 = Pd.x,  ph1 = Pd.y;
            float gx0 = Ga.x, gy0 = Ga.y, gw0 = Gb_.x, gh0 = Gb_.y;
            float gx1 = Gc.x, gy1 = Gc.y, gw1 = Gd.x,  gh1 = Gd.y;

            // IoU in 7x-scaled coords (scale-invariant)
            float pcx0 = sx0 + colf, pcy0 = sy0 + rowf;
            float pcx1 = sx1 + colf, pcy1 = sy1 + rowf;
            float gcx0 = gx0 + colf, gcy0 = gy0 + rowf;
            float gcx1 = gx1 + colf, gcy1 = gy1 + rowf;
            const float H = 3.5f;

            float pl0 = pcx0 - pw0 * H, pt0 = pcy0 - ph0 * H;
            float pr_0 = pcx0 + pw0 * H, pb0 = pcy0 + ph0 * H;
            float pl1 = pcx1 - pw1 * H, pt1 = pcy1 - ph1 * H;
            float pr_1 = pcx1 + pw1 * H, pb1 = pcy1 + ph1 * H;
            float gl0 = gcx0 - gw0 * H, gt0 = gcy0 - gh0 * H;
            float gr0 = gcx0 + gw0 * H, gb0 = gcy0 + gh0 * H;
            float gl1 = gcx1 - gw1 * H, gt1 = gcy1 - gh1 * H;
            float gr1 = gcx1 + gw1 * H, gb1 = gcy1 + gh1 * H;

            float ap0 = (pr_0 - pl0) * (pb0 - pt0);
            float ap1 = (pr_1 - pl1) * (pb1 - pt1);
            float ag0 = (gr0 - gl0) * (gb0 - gt0);
            float ag1 = (gr1 - gl1) * (gb1 - gt1);

            float n00, d00, n10, d10, n01, d01, n11, d11;
            iou_nd(pl0, pt0, pr_0, pb0, gl0, gt0, gr0, gb0, ap0, ag0, n00, d00);
            iou_nd(pl1, pt1, pr_1, pb1, gl0, gt0, gr0, gb0, ap1, ag0, n10, d10);
            iou_nd(pl0, pt0, pr_0, pb0, gl1, gt1, gr1, gb1, ap0, ag1, n01, d01);
            iou_nd(pl1, pt1, pr_1, pb1, gl1, gt1, gr1, gb1, ap1, ag1, n11, d11);

            bool ind0 = n10 * d00 > n00 * d10;   // argmax via cross-mult (d > 0)
            bool ind1 = n11 * d01 > n01 * d11;

            bool same_g   = (gx0 == gx1) && (gy0 == gy1) && (gw0 == gw1) && (gh0 == gh1);
            bool same_ind = (ind0 == ind1);

            float sqw0 = sqrt_ap(fabsf(pw0)), sqh0 = sqrt_ap(fabsf(ph0));
            float sqw1 = sqrt_ap(fabsf(pw1)), sqh1 = sqrt_ap(fabsf(ph1));
            float sgw0 = sqrt_ap(gw0), sgh0 = sqrt_ap(gh0);
            float sgw1 = sqrt_ap(gw1), sgh1 = sqrt_ap(gh1);

            #define BLOSS(px, py, qw, qh, qx, qy, rw, rh)                         \
                ((px - qx) * (px - qx) + (py - qy) * (py - qy) +                  \
                 (qw - rw) * (qw - rw) + (qh - rh) * (qh - rh))
            float l00 = BLOSS(sx0, sy0, sqw0, sqh0, gx0, gy0, sgw0, sgh0);
            float l10 = BLOSS(sx1, sy1, sqw1, sqh1, gx0, gy0, sgw0, sgh0);
            float l01 = BLOSS(sx0, sy0, sqw0, sqh0, gx1, gy1, sgw1, sgh1);
            float l11 = BLOSS(sx1, sy1, sqw1, sqh1, gx1, gy1, sgw1, sgh1);
            #undef BLOSS

            float lA = ind0 ? l10 : l00;
            float lB = l00 + l11;
            float lC = lA + (ind1 ? l11 : l01);
            float box_cell = same_g ? lA : (same_ind ? lB : lC);

            float pc0 = Pe.x, pc1 = Pe.y;
            float sp8 = softp(pc0), sp9 = softp(pc1);
            float confA  = ind1 ? (sp9 - pc1) : (sp8 - pc0);
            float confBC = (sp8 - pc0) + (sp9 - pc1);
            float conf_cell = same_g ? confA : confBC;

            float lossP = 5.0f * box_cell + conf_cell;
            float lossN = 0.5f * (sp8 + sp9);
            acc += pos ? lossP : (zero ? lossN : 0.0f);
        } else {
            // ===== cls loss: 320 float2 elems of this tile, 10 per lane =====
            const float2* Pc2 = reinterpret_cast<const float2*>(sb);
            const float2* Gc2 = reinterpret_cast<const float2*>(sb + WT_FLOATS);
            const float*  gfl = sb + WT_FLOATS;
            int ci = lane / 10;
            int h  = lane - 10 * ci;
            float f0 = 1.0f, f1 = 1.0f, dot = 0.0f;
            #pragma unroll
            for (int k = 0; k < 10; k++) {
                bool ok = ci < nv;
                int cc = ok ? ci : 0;
                int fi = cc * 15 + 5 + h;
                float2 pv = Pc2[fi];
                float2 gv = Gc2[fi];
                float conf = gfl[cc * CELL_F + 8];
                bool m = ok && (conf > 0.0f);
                float fac = (1.0f + __expf(pv.x)) * (1.0f + __expf(pv.y));
                if (k & 1) f1 *= m ? fac : 1.0f;
                else       f0 *= m ? fac : 1.0f;
                dot += m ? (pv.x * gv.x + pv.y * gv.y) : 0.0f;
                h += 2; ci += 3; if (h >= 10) { h -= 10; ci += 1; }   // +32 elems
            }
            acc += __logf(f0) + __logf(f1) - dot;
        }

        asm volatile("bar.sync %0, 64;" :: "r"(barid) : "memory");   // pair done reading
        prefetch(it & 1, t + 2 * S);             // exactly one commit
    }

    // ---------- block reduction ----------
    float loss = acc;
    #pragma unroll
    for (int o = 16; o > 0; o >>= 1) loss += __shfl_xor_sync(0xFFFFFFFFu, loss, o);
    if (lane == 0) wsum[w] = loss;
    __syncthreads();
    if (tid == 0) {
        float bs = 0.0f;
        #pragma unroll
        for (int ww = 0; ww < TPB / 32; ww++) bs += wsum[ww];
        g_partials[blockIdx.x] = bs;
        __threadfence();
        s_ticket = atomicAdd(&g_count, 1u);
    }
    __syncthreads();

    // ---------- last block finalizes (fixed order; self-resetting; graph-safe) ----------
    if (s_ticket == gridDim.x - 1) {
        __threadfence();
        volatile float* vp = g_partials;
        double dacc = 0.0;
        for (int i = tid; i < (int)gridDim.x; i += TPB) dacc += (double)vp[i];
        #pragma unroll
        for (int o = 16; o > 0; o >>= 1) dacc += __shfl_xor_sync(0xFFFFFFFFu, dacc, o);
        if ((tid & 31) == 0) wdsum[tid >> 5] = dacc;
        __syncthreads();
        if (tid == 0) {
            double tot = 0.0;
            #pragma unroll
            for (int ww = 0; ww < TPB / 32; ww++) tot += wdsum[ww];
            *out = (float)(tot * inv_batch);
            g_count = 0;                 // restore for next graph replay
        }
    }
}

extern "C" void kernel_launch(void* const* d_in, const int* in_sizes, int n_in,
                              void* d_out, int out_size) {
    const float* p = (const float*)d_in[0];
    const float* g = (const float*)d_in[1];
    int total  = in_sizes[0];            // B*7*7*30
    int ncells = total / CELL_F;         // B*49
    int batch  = ncells / 49;
    int ntiles = (ncells + WT - 1) / WT;
    int nb = GRID_MAX;
    int nb_need = (ntiles + 2 * NPAIR - 1) / (2 * NPAIR);
    if (nb > nb_need) nb = nb_need;
    if (nb < 1) nb = 1;

    static int attr_set = 0;
    if (!attr_set) {
        cudaFuncSetAttribute(k_main, cudaFuncAttributePreferredSharedMemoryCarveout, 100);
        attr_set = 1;
    }
    k_main<<<nb, TPB>>>(p, g, ncells, ntiles, (float*)d_out, 1.0 / (double)batch);
}

// round 14
// speedup vs baseline: 1.3570x; 1.2357x over previous
#include <cuda_runtime.h>
#include <cstdint>

#define CELL_F        30
#define TPB           64
#define NWARP         (TPB / 32)               // 2
#define WT_CELLS      32                       // cells per warp-tile
#define WT_FLOATS     (WT_CELLS * CELL_F)      // 960 per tensor
#define WT_F4         (WT_FLOATS / 4)          // 240
#define STAGE_FLOATS  (2 * WT_FLOATS)          // 1920  (p | g)
#define STAGE_BYTES   (STAGE_FLOATS * 4)       // 7680
#define WARP_FLOATS   (2 * STAGE_FLOATS)       // 3840 (2 stages)
#define SMEM_FLOATS   (NWARP * WARP_FLOATS)    // 7680 floats = 30,720 B/block
#define GRID_MAX      1036                     // 7 blocks/SM * 148 SMs

__device__ float        g_partials[2048];
__device__ unsigned int g_count = 0;

__device__ __forceinline__ void cp_async16(uint32_t saddr, const void* gaddr) {
    asm volatile("cp.async.cg.shared.global [%0], [%1], 16;\n"
                 :: "r"(saddr), "l"(gaddr) : "memory");
}
__device__ __forceinline__ void cp_commit() {
    asm volatile("cp.async.commit_group;\n" ::: "memory");
}
__device__ __forceinline__ void cp_wait1() {
    asm volatile("cp.async.wait_group 1;\n" ::: "memory");
}

__device__ __forceinline__ float softp(float x) {      // log(1+e^x), |x| small
    return __logf(1.0f + __expf(x));
}
__device__ __forceinline__ float sigm(float x) {
    return __fdividef(1.0f, 1.0f + __expf(-x));
}
__device__ __forceinline__ float sqrt_ap(float x) {
    float r; asm("sqrt.approx.f32 %0, %1;" : "=f"(r) : "f"(x)); return r;
}
__device__ __forceinline__ float iou_f(float al, float at, float ar, float ab,
                                       float bl, float bt, float br, float bb,
                                       float area_a, float area_b) {
    float ltx = fmaxf(al, bl), lty = fmaxf(at, bt);
    float rbx = fminf(ar, br), rby = fminf(ab, bb);
    float wx = fmaxf(rbx - ltx, 0.0f), wy = fmaxf(rby - lty, 0.0f);
    float inter = wx * wy;
    return __fdividef(inter, area_a + area_b - inter + 1e-7f);
}

__global__ void __launch_bounds__(TPB)
k_main(const float* __restrict__ p, const float* __restrict__ g,
       int ncells, int ntiles, float* __restrict__ out, double inv_batch) {
    __shared__ float s[SMEM_FLOATS];          // [warp][stage][p:960|g:960]
    __shared__ float wsum[NWARP];
    __shared__ unsigned int s_ticket;

    const int tid  = threadIdx.x;
    const int w    = tid >> 5;
    const int lane = tid & 31;
    float* swp = s + w * WARP_FLOATS;         // this warp's 2-stage buffer
    const uint32_t swb = (uint32_t)__cvta_generic_to_shared(swp);

    const int S  = gridDim.x * NWARP;         // warp-streams
    const int ws = blockIdx.x * NWARP + w;

    // ---- prefetch one warp-tile into a stage (always commits exactly one group) ----
    auto prefetch = [&](int stage, int t) {
        if (t < ntiles) {
            const float4* p4 = reinterpret_cast<const float4*>(p) + (long long)t * WT_F4;
            const float4* g4 = reinterpret_cast<const float4*>(g) + (long long)t * WT_F4;
            uint32_t sp_ = swb + (uint32_t)stage * STAGE_BYTES;
            uint32_t sg_ = sp_ + WT_FLOATS * 4;
            if ((t + 1) * WT_CELLS <= ncells) {
                #pragma unroll
                for (int k = 0; k < 8; k++) {
                    int i = lane + k * 32;
                    if (i < WT_F4) {
                        cp_async16(sp_ + i * 16, p4 + i);
                        cp_async16(sg_ + i * 16, g4 + i);
                    }
                }
            } else {            // ragged final tile: scalar staging
                int nf = (ncells - t * WT_CELLS) * CELL_F;
                float* sd = swp + stage * STAGE_FLOATS;
                const float* pb = p + (long long)t * WT_FLOATS;
                const float* gb = g + (long long)t * WT_FLOATS;
                for (int ff = lane; ff < nf; ff += 32) {
                    sd[ff]             = pb[ff];
                    sd[WT_FLOATS + ff] = gb[ff];
                }
            }
        }
        cp_commit();
    };

    prefetch(0, ws);
    prefetch(1, ws + S);

    float acc = 0.0f;
    int it = 0;
    for (int t = ws; t < ntiles; t += S, it++) {
        cp_wait1();
        __syncwarp();

        const float* sb = swp + (it & 1) * STAGE_FLOATS;
        int cell = t * WT_CELLS + lane;
        if (cell < ncells) {
            const float2* P2 = reinterpret_cast<const float2*>(sb) + lane * 15;
            const float2* G2 = reinterpret_cast<const float2*>(sb + WT_FLOATS) + lane * 15;

            float2 Pa = P2[0], Pb_ = P2[1], Pc = P2[2], Pd = P2[3], Pe = P2[4];
            float2 Ga = G2[0], Gb_ = G2[1], Gc = G2[2], Gd = G2[3], Ge = G2[4];
            float conf_g = Ge.x;

            // ---- class BCE via log of products (2 groups of 10) ----
            float pr0 = 1.0f, pr1 = 1.0f, spg = 0.0f;
            #pragma unroll
            for (int k = 5; k < 10; k++) {
                float2 pv = P2[k], gv = G2[k];
                pr0 *= (1.0f + __expf(pv.x)) * (1.0f + __expf(pv.y));
                spg += pv.x * gv.x + pv.y * gv.y;
            }
            #pragma unroll
            for (int k = 10; k < 15; k++) {
                float2 pv = P2[k], gv = G2[k];
                pr1 *= (1.0f + __expf(pv.x)) * (1.0f + __expf(pv.y));
                spg += pv.x * gv.x + pv.y * gv.y;
            }
            float cls = __logf(pr0) + __logf(pr1) - spg;

            int ij = cell % 49;
            int r  = ij / 7;
            int c  = ij - r * 7;
            float colf = (float)c, rowf = (float)r;

            float sx0 = sigm(Pa.x), sy0 = sigm(Pa.y), pw0 = Pb_.x, ph0 = Pb_.y;
            float sx1 = sigm(Pc.x), sy1 = sigm(Pc.y), pw1 = Pd.x,  ph1 = Pd.y;
            float gx0 = Ga.x, gy0 = Ga.y, gw0 = Gb_.x, gh0 = Gb_.y;
            float gx1 = Gc.x, gy1 = Gc.y, gw1 = Gd.x,  gh1 = Gd.y;

            // IoU in 7x-scaled coords (scale-invariant)
            float pcx0 = sx0 + colf, pcy0 = sy0 + rowf;
            float pcx1 = sx1 + colf, pcy1 = sy1 + rowf;
            float gcx0 = gx0 + colf, gcy0 = gy0 + rowf;
            float gcx1 = gx1 + colf, gcy1 = gy1 + rowf;
            const float H = 3.5f;

            float pl0 = pcx0 - pw0 * H, pt0 = pcy0 - ph0 * H;
            float pr_0 = pcx0 + pw0 * H, pb0 = pcy0 + ph0 * H;
            float pl1 = pcx1 - pw1 * H, pt1 = pcy1 - ph1 * H;
            float pr_1 = pcx1 + pw1 * H, pb1 = pcy1 + ph1 * H;
            float gl0 = gcx0 - gw0 * H, gt0 = gcy0 - gh0 * H;
            float gr0 = gcx0 + gw0 * H, gb0 = gcy0 + gh0 * H;
            float gl1 = gcx1 - gw1 * H, gt1 = gcy1 - gh1 * H;
            float gr1 = gcx1 + gw1 * H, gb1 = gcy1 + gh1 * H;

            float ap0 = (pr_0 - pl0) * (pb0 - pt0);
            float ap1 = (pr_1 - pl1) * (pb1 - pt1);
            float ag0 = (gr0 - gl0) * (gb0 - gt0);
            float ag1 = (gr1 - gl1) * (gb1 - gt1);

            float i00 = iou_f(pl0, pt0, pr_0, pb0, gl0, gt0, gr0, gb0, ap0, ag0);
            float i10 = iou_f(pl1, pt1, pr_1, pb1, gl0, gt0, gr0, gb0, ap1, ag0);
            float i01 = iou_f(pl0, pt0, pr_0, pb0, gl1, gt1, gr1, gb1, ap0, ag1);
            float i11 = iou_f(pl1, pt1, pr_1, pb1, gl1, gt1, gr1, gb1, ap1, ag1);

            bool ind0 = i10 > i00;     // jnp.argmax: first max wins
            bool ind1 = i11 > i01;

            bool same_g   = (gx0 == gx1) && (gy0 == gy1) && (gw0 == gw1) && (gh0 == gh1);
            bool same_ind = (ind0 == ind1);

            float sqw0 = sqrt_ap(fabsf(pw0)), sqh0 = sqrt_ap(fabsf(ph0));
            float sqw1 = sqrt_ap(fabsf(pw1)), sqh1 = sqrt_ap(fabsf(ph1));
            float sgw0 = sqrt_ap(gw0), sgh0 = sqrt_ap(gh0);
            float sgw1 = sqrt_ap(gw1), sgh1 = sqrt_ap(gh1);

            #define BLOSS(px, py, qw, qh, qx, qy, rw, rh)                         \
                ((px - qx) * (px - qx) + (py - qy) * (py - qy) +                  \
                 (qw - rw) * (qw - rw) + (qh - rh) * (qh - rh))
            float l00 = BLOSS(sx0, sy0, sqw0, sqh0, gx0, gy0, sgw0, sgh0);
            float l10 = BLOSS(sx1, sy1, sqw1, sqh1, gx0, gy0, sgw0, sgh0);
            float l01 = BLOSS(sx0, sy0, sqw0, sqh0, gx1, gy1, sgw1, sgh1);
            float l11 = BLOSS(sx1, sy1, sqw1, sqh1, gx1, gy1, sgw1, sgh1);
            #undef BLOSS

            float lA = ind0 ? l10 : l00;
            float lB = l00 + l11;
            float lC = lA + (ind1 ? l11 : l01);
            float box_cell = same_g ? lA : (same_ind ? lB : lC);

            float pc0 = Pe.x, pc1 = Pe.y;
            float sp8 = softp(pc0), sp9 = softp(pc1);
            float confA  = ind1 ? (sp9 - pc1) : (sp8 - pc0);
            float confBC = (sp8 - pc0) + (sp9 - pc1);
            float conf_cell = same_g ? confA : confBC;

            float lossP = 5.0f * box_cell + conf_cell + cls;
            float lossN = 0.5f * (sp8 + sp9);
            acc += (conf_g > 0.0f) ? lossP : ((conf_g == 0.0f) ? lossN : 0.0f);
        }

        __syncwarp();                    // warp done reading this stage
        prefetch(it & 1, t + 2 * S);     // exactly one commit
    }

    // ---------- block reduction (once per block) ----------
    float loss = acc;
    #pragma unroll
    for (int o = 16; o > 0; o >>= 1) loss += __shfl_xor_sync(0xFFFFFFFFu, loss, o);
    if (lane == 0) wsum[w] = loss;
    __syncthreads();
    if (tid == 0) {
        float bs = 0.0f;
        #pragma unroll
        for (int ww = 0; ww < NWARP; ww++) bs += wsum[ww];
        g_partials[blockIdx.x] = bs;
        __threadfence();
        s_ticket = atomicAdd(&g_count, 1u);
    }
    __syncthreads();

    // ---------- last block finalizes (fixed order; self-resetting; graph-safe) ----------
    if (s_ticket == gridDim.x - 1) {
        __threadfence();
        volatile float* vp = g_partials;
        double dacc = 0.0;
        for (int i = tid; i < (int)gridDim.x; i += TPB) dacc += (double)vp[i];
        #pragma unroll
        for (int o = 16; o > 0; o >>= 1) dacc += __shfl_xor_sync(0xFFFFFFFFu, dacc, o);
        __shared__ double wd[NWARP];
        if (lane == 0) wd[w] = dacc;
        __syncthreads();
        if (tid == 0) {
            double tot = 0.0;
            #pragma unroll
            for (int ww = 0; ww < NWARP; ww++) tot += wd[ww];
            *out = (float)(tot * inv_batch);
            g_count = 0;                 // restore for next graph replay
        }
    }
}

extern "C" void kernel_launch(void* const* d_in, const int* in_sizes, int n_in,
                              void* d_out, int out_size) {
    const float* p = (const float*)d_in[0];
    const float* g = (const float*)d_in[1];
    int total  = in_sizes[0];            // B*7*7*30
    int ncells = total / CELL_F;         // B*49
    int batch  = ncells / 49;
    int ntiles = (ncells + WT_CELLS - 1) / WT_CELLS;   // warp-tiles of 32 cells
    int nstreams_needed = (ntiles + 1) / 2;            // at least 1 tile per 2 stages
    int nb = GRID_MAX;
    if (nb * NWARP > nstreams_needed) {
        nb = (nstreams_needed + NWARP - 1) / NWARP;
        if (nb < 1) nb = 1;
    }

    k_main<<<nb, TPB>>>(p, g, ncells, ntiles, (float*)d_out, 1.0 / (double)batch);
}

// round 15
// speedup vs baseline: 1.3957x; 1.0285x over previous
#include <cuda_runtime.h>
#include <cstdint>

#define CELL_F        30
#define TPB           64
#define NWARP         (TPB / 32)               // 2
#define WT_CELLS      32                       // cells per warp-tile
#define WT_FLOATS     (WT_CELLS * CELL_F)      // 960 per tensor
#define WT_F4         (WT_FLOATS / 4)          // 240
#define STAGE_FLOATS  (2 * WT_FLOATS)          // 1920  (p | g)
#define STAGE_BYTES   (STAGE_FLOATS * 4)       // 7680
#define WARP_FLOATS   (2 * STAGE_FLOATS)       // 3840 (2 stages)
#define SMEM_FLOATS   (NWARP * WARP_FLOATS)    // 7680 floats = 30,720 B/block
#define GRID_MAX      1036                     // 7 blocks/SM * 148 SMs

__device__ float        g_partials[2048];
__device__ unsigned int g_count = 0;

__device__ __forceinline__ void cp_async16(uint32_t saddr, const void* gaddr) {
    asm volatile("cp.async.cg.shared.global [%0], [%1], 16;\n"
                 :: "r"(saddr), "l"(gaddr) : "memory");
}
__device__ __forceinline__ void cp_commit() {
    asm volatile("cp.async.commit_group;\n" ::: "memory");
}
__device__ __forceinline__ void cp_wait1() {
    asm volatile("cp.async.wait_group 1;\n" ::: "memory");
}

__device__ __forceinline__ float softp(float x) {      // log(1+e^x), |x| small
    return __logf(1.0f + __expf(x));
}
__device__ __forceinline__ float sigm(float x) {
    return __fdividef(1.0f, 1.0f + __expf(-x));
}
__device__ __forceinline__ float sqrt_ap(float x) {
    float r; asm("sqrt.approx.f32 %0, %1;" : "=f"(r) : "f"(x)); return r;
}
__device__ __forceinline__ float iou_f(float al, float at, float ar, float ab,
                                       float bl, float bt, float br, float bb,
                                       float area_a, float area_b) {
    float ltx = fmaxf(al, bl), lty = fmaxf(at, bt);
    float rbx = fminf(ar, br), rby = fminf(ab, bb);
    float wx = fmaxf(rbx - ltx, 0.0f), wy = fmaxf(rby - lty, 0.0f);
    float inter = wx * wy;
    return __fdividef(inter, area_a + area_b - inter + 1e-7f);
}

__global__ void __launch_bounds__(TPB)
k_main(const float* __restrict__ p, const float* __restrict__ g,
       int ncells, int ntiles, float* __restrict__ out, double inv_batch) {
    __shared__ float s[SMEM_FLOATS];          // [warp][stage][p:960|g:960]
    __shared__ float wsum[NWARP];
    __shared__ unsigned int s_ticket;

    const int tid  = threadIdx.x;
    const int w    = tid >> 5;
    const int lane = tid & 31;
    float* swp = s + w * WARP_FLOATS;         // this warp's 2-stage buffer
    const uint32_t swb = (uint32_t)__cvta_generic_to_shared(swp);

    const int S  = gridDim.x * NWARP;         // total warp-streams
    const int ws = blockIdx.x * NWARP + w;

    // ---- balanced contiguous partition: tiles [lo, hi) for this stream ----
    const int lo = (int)(((long long)ws       * ntiles) / S);
    const int hi = (int)(((long long)(ws + 1) * ntiles) / S);

    // ---- prefetch one warp-tile into a stage (always commits exactly one group) ----
    auto prefetch = [&](int stage, int t) {
        if (t < hi) {
            const float4* p4 = reinterpret_cast<const float4*>(p) + (long long)t * WT_F4;
            const float4* g4 = reinterpret_cast<const float4*>(g) + (long long)t * WT_F4;
            uint32_t sp_ = swb + (uint32_t)stage * STAGE_BYTES;
            uint32_t sg_ = sp_ + WT_FLOATS * 4;
            if ((t + 1) * WT_CELLS <= ncells) {
                #pragma unroll
                for (int k = 0; k < 8; k++) {
                    int i = lane + k * 32;
                    if (i < WT_F4) {
                        cp_async16(sp_ + i * 16, p4 + i);
                        cp_async16(sg_ + i * 16, g4 + i);
                    }
                }
            } else {            // ragged final tile: scalar staging
                int nf = (ncells - t * WT_CELLS) * CELL_F;
                float* sd = swp + stage * STAGE_FLOATS;
                const float* pb = p + (long long)t * WT_FLOATS;
                const float* gb = g + (long long)t * WT_FLOATS;
                for (int ff = lane; ff < nf; ff += 32) {
                    sd[ff]             = pb[ff];
                    sd[WT_FLOATS + ff] = gb[ff];
                }
            }
        }
        cp_commit();
    };

    prefetch(0, lo);
    prefetch(1, lo + 1);

    float acc = 0.0f;
    for (int t = lo; t < hi; t++) {
        cp_wait1();
        __syncwarp();

        const float* sb = swp + ((t - lo) & 1) * STAGE_FLOATS;
        int cell = t * WT_CELLS + lane;
        if (cell < ncells) {
            const float2* P2 = reinterpret_cast<const float2*>(sb) + lane * 15;
            const float2* G2 = reinterpret_cast<const float2*>(sb + WT_FLOATS) + lane * 15;

            float2 Pa = P2[0], Pb_ = P2[1], Pc = P2[2], Pd = P2[3], Pe = P2[4];
            float2 Ga = G2[0], Gb_ = G2[1], Gc = G2[2], Gd = G2[3], Ge = G2[4];
            float conf_g = Ge.x;

            // ---- class BCE via log of products (2 groups of 10) ----
            float pr0 = 1.0f, pr1 = 1.0f, spg = 0.0f;
            #pragma unroll
            for (int k = 5; k < 10; k++) {
                float2 pv = P2[k], gv = G2[k];
                pr0 *= (1.0f + __expf(pv.x)) * (1.0f + __expf(pv.y));
                spg += pv.x * gv.x + pv.y * gv.y;
            }
            #pragma unroll
            for (int k = 10; k < 15; k++) {
                float2 pv = P2[k], gv = G2[k];
                pr1 *= (1.0f + __expf(pv.x)) * (1.0f + __expf(pv.y));
                spg += pv.x * gv.x + pv.y * gv.y;
            }
            float cls = __logf(pr0) + __logf(pr1) - spg;

            int ij = cell % 49;
            int r  = ij / 7;
            int c  = ij - r * 7;
            float colf = (float)c, rowf = (float)r;

            float sx0 = sigm(Pa.x), sy0 = sigm(Pa.y), pw0 = Pb_.x, ph0 = Pb_.y;
            float sx1 = sigm(Pc.x), sy1 = sigm(Pc.y), pw1 = Pd.x,  ph1 = Pd.y;
            float gx0 = Ga.x, gy0 = Ga.y, gw0 = Gb_.x, gh0 = Gb_.y;
            float gx1 = Gc.x, gy1 = Gc.y, gw1 = Gd.x,  gh1 = Gd.y;

            // IoU in 7x-scaled coords (scale-invariant)
            float pcx0 = sx0 + colf, pcy0 = sy0 + rowf;
            float pcx1 = sx1 + colf, pcy1 = sy1 + rowf;
            float gcx0 = gx0 + colf, gcy0 = gy0 + rowf;
            float gcx1 = gx1 + colf, gcy1 = gy1 + rowf;
            const float H = 3.5f;

            float pl0 = pcx0 - pw0 * H, pt0 = pcy0 - ph0 * H;
            float pr_0 = pcx0 + pw0 * H, pb0 = pcy0 + ph0 * H;
            float pl1 = pcx1 - pw1 * H, pt1 = pcy1 - ph1 * H;
            float pr_1 = pcx1 + pw1 * H, pb1 = pcy1 + ph1 * H;
            float gl0 = gcx0 - gw0 * H, gt0 = gcy0 - gh0 * H;
            float gr0 = gcx0 + gw0 * H, gb0 = gcy0 + gh0 * H;
            float gl1 = gcx1 - gw1 * H, gt1 = gcy1 - gh1 * H;
            float gr1 = gcx1 + gw1 * H, gb1 = gcy1 + gh1 * H;

            float ap0 = (pr_0 - pl0) * (pb0 - pt0);
            float ap1 = (pr_1 - pl1) * (pb1 - pt1);
            float ag0 = (gr0 - gl0) * (gb0 - gt0);
            float ag1 = (gr1 - gl1) * (gb1 - gt1);

            float i00 = iou_f(pl0, pt0, pr_0, pb0, gl0, gt0, gr0, gb0, ap0, ag0);
            float i10 = iou_f(pl1, pt1, pr_1, pb1, gl0, gt0, gr0, gb0, ap1, ag0);
            float i01 = iou_f(pl0, pt0, pr_0, pb0, gl1, gt1, gr1, gb1, ap0, ag1);
            float i11 = iou_f(pl1, pt1, pr_1, pb1, gl1, gt1, gr1, gb1, ap1, ag1);

            bool ind0 = i10 > i00;     // jnp.argmax: first max wins
            bool ind1 = i11 > i01;

            bool same_g   = (gx0 == gx1) && (gy0 == gy1) && (gw0 == gw1) && (gh0 == gh1);
            bool same_ind = (ind0 == ind1);

            float sqw0 = sqrt_ap(fabsf(pw0)), sqh0 = sqrt_ap(fabsf(ph0));
            float sqw1 = sqrt_ap(fabsf(pw1)), sqh1 = sqrt_ap(fabsf(ph1));
            float sgw0 = sqrt_ap(gw0), sgh0 = sqrt_ap(gh0);
            float sgw1 = sqrt_ap(gw1), sgh1 = sqrt_ap(gh1);

            #define BLOSS(px, py, qw, qh, qx, qy, rw, rh)                         \
                ((px - qx) * (px - qx) + (py - qy) * (py - qy) +                  \
                 (qw - rw) * (qw - rw) + (qh - rh) * (qh - rh))
            float l00 = BLOSS(sx0, sy0, sqw0, sqh0, gx0, gy0, sgw0, sgh0);
            float l10 = BLOSS(sx1, sy1, sqw1, sqh1, gx0, gy0, sgw0, sgh0);
            float l01 = BLOSS(sx0, sy0, sqw0, sqh0, gx1, gy1, sgw1, sgh1);
            float l11 = BLOSS(sx1, sy1, sqw1, sqh1, gx1, gy1, sgw1, sgh1);
            #undef BLOSS

            float lA = ind0 ? l10 : l00;
            float lB = l00 + l11;
            float lC = lA + (ind1 ? l11 : l01);
            float box_cell = same_g ? lA : (same_ind ? lB : lC);

            float pc0 = Pe.x, pc1 = Pe.y;
            float sp8 = softp(pc0), sp9 = softp(pc1);
            float confA  = ind1 ? (sp9 - pc1) : (sp8 - pc0);
            float confBC = (sp8 - pc0) + (sp9 - pc1);
            float conf_cell = same_g ? confA : confBC;

            float lossP = 5.0f * box_cell + conf_cell + cls;
            float lossN = 0.5f * (sp8 + sp9);
            acc += (conf_g > 0.0f) ? lossP : ((conf_g == 0.0f) ? lossN : 0.0f);
        }

        __syncwarp();                    // warp done reading this stage
        prefetch((t - lo) & 1, t + 2);   // exactly one commit
    }

    // ---------- block reduction (once per block) ----------
    float loss = acc;
    #pragma unroll
    for (int o = 16; o > 0; o >>= 1) loss += __shfl_xor_sync(0xFFFFFFFFu, loss, o);
    if (lane == 0) wsum[w] = loss;
    __syncthreads();
    if (tid == 0) {
        float bs = 0.0f;
        #pragma unroll
        for (int ww = 0; ww < NWARP; ww++) bs += wsum[ww];
        g_partials[blockIdx.x] = bs;
        __threadfence();
        s_ticket = atomicAdd(&g_count, 1u);
    }
    __syncthreads();

    // ---------- last block finalizes (fixed order; self-resetting; graph-safe) ----------
    if (s_ticket == gridDim.x - 1) {
        __threadfence();
        volatile float* vp = g_partials;
        double dacc = 0.0;
        for (int i = tid; i < (int)gridDim.x; i += TPB) dacc += (double)vp[i];
        #pragma unroll
        for (int o = 16; o > 0; o >>= 1) dacc += __shfl_xor_sync(0xFFFFFFFFu, dacc, o);
        __shared__ double wd[NWARP];
        if (lane == 0) wd[w] = dacc;
        __syncthreads();
        if (tid == 0) {
            double tot = 0.0;
            #pragma unroll
            for (int ww = 0; ww < NWARP; ww++) tot += wd[ww];
            *out = (float)(tot * inv_batch);
            g_count = 0;                 // restore for next graph replay
        }
    }
}

extern "C" void kernel_launch(void* const* d_in, const int* in_sizes, int n_in,
                              void* d_out, int out_size) {
    const float* p = (const float*)d_in[0];
    const float* g = (const float*)d_in[1];
    int total  = in_sizes[0];            // B*7*7*30
    int ncells = total / CELL_F;         // B*49
    int batch  = ncells / 49;
    int ntiles = (ncells + WT_CELLS - 1) / WT_CELLS;   // warp-tiles of 32 cells
    int nstreams_needed = (ntiles + 1) / 2;            // at least 1 tile per 2 stages
    int nb = GRID_MAX;
    if (nb * NWARP > nstreams_needed) {
        nb = (nstreams_needed + NWARP - 1) / NWARP;
        if (nb < 1) nb = 1;
    }

    k_main<<<nb, TPB>>>(p, g, ncells, ntiles, (float*)d_out, 1.0 / (double)batch);
}